// round 10
// baseline (speedup 1.0000x reference)
#include <cuda_runtime.h>
#include <cuda_bf16.h>
#include <cstdint>
#include <cstddef>

#define NN 512
#define BN 2048
#define FD 64
#define EPSV 1e-14f

typedef unsigned long long ull;
typedef unsigned int u32;

// ---------------- scratch ----------------
__device__ float g_pjewT[BN * FD];   // [b][k][j] transposed
__device__ float g_pi_ew[BN * FD];
__device__ float g_pjesT[BN * FD];   // [b][h][j] transposed
__device__ float g_pi_es[BN * FD];
__device__ float g_pj_sa[BN];
__device__ float g_pi_sa[BN];

// ---------------- helpers ----------------
__device__ __forceinline__ float tanh_hw(float v) {
    float r; asm("tanh.approx.f32 %0, %1;" : "=f"(r) : "f"(v)); return r;
}
__device__ __forceinline__ float silu_hw(float v) {
    float m = 0.5f * v;
    return fmaf(m, tanh_hw(m), m);
}
__device__ __forceinline__ u32 tf32r(float f) {
    u32 r; asm("cvt.rna.tf32.f32 %0, %1;" : "=r"(r) : "f"(f)); return r;
}

__device__ __forceinline__ void mma_tf32_16x8x8(float d[4], const u32 a[4], u32 b0, u32 b1) {
    asm volatile("mma.sync.aligned.m16n8k8.row.col.f32.tf32.tf32.f32 "
        "{%0,%1,%2,%3}, {%4,%5,%6,%7}, {%8,%9}, {%0,%1,%2,%3};"
        : "+f"(d[0]), "+f"(d[1]), "+f"(d[2]), "+f"(d[3])
        : "r"(a[0]), "r"(a[1]), "r"(a[2]), "r"(a[3]), "r"(b0), "r"(b1));
}

#define STS128S(ad, r0, r1, r2, r3) \
    asm volatile("st.shared.v4.b32 [%0], {%1,%2,%3,%4};" :: "r"(ad), "r"(r0), "r"(r1), "r"(r2), "r"(r3) : "memory")

#define APAD 68   // 272B rows: 16B-aligned v4 stores; A-frag banks (4*r4+c4) distinct; agg banks (4*jj+lane) distinct

struct __align__(16) SMEM {
    float A[8][16 * APAD];   // per-warp he subtile (tf32 bits), [j(16)][h(64)]
    float Bp[8 * FD * 8];    // W_c1 pair-packed: [kt(8)][m(64)][c4(4)][kk(2)]  (16KB)
    float4 xmxv[NN];         // (dx, dy, dz, inv2)
    float filt[NN];
    float sw[NN];
    float piew[FD], pies[FD], wes0[FD], bc1[FD], wc2[FD];
    float attp[4][FD][3];
    float aggp[8][FD];
    float agg[FD], attn[FD];
    float xp[8][3];
    float red[8];
    float scal;
};

// ---------------- kernel A: node-level projections ----------------
__global__ void sake_pre(const float* __restrict__ h,
                         const float* __restrict__ W_ew,
                         const float* __restrict__ W_es,
                         const float* __restrict__ W_sa) {
    int n = blockIdx.x;
    int k = threadIdx.x;
    __shared__ float sh[FD];
    __shared__ float sp1[FD], sp2[FD];
    sh[k] = h[n * FD + k];
    __syncthreads();
    float a_jew = 0.f, a_iew = 0.f, a_jes = 0.f, a_ies = 0.f;
#pragma unroll 8
    for (int f = 0; f < FD; f++) {
        float hf = sh[f];
        a_jew = fmaf(hf, W_ew[f * FD + k], a_jew);
        a_iew = fmaf(hf, W_ew[(FD + f) * FD + k], a_iew);
        a_jes = fmaf(hf, W_es[(1 + f) * FD + k], a_jes);
        a_ies = fmaf(hf, W_es[(1 + FD + f) * FD + k], a_ies);
    }
    int b = n >> 9, j = n & 511;
    g_pjewT[(b * FD + k) * NN + j] = a_jew;
    g_pi_ew[n * FD + k] = a_iew;
    g_pjesT[(b * FD + k) * NN + j] = a_jes;
    g_pi_es[n * FD + k] = a_ies;
    sp1[k] = sh[k] * W_sa[k];
    sp2[k] = sh[k] * W_sa[FD + k];
    __syncthreads();
    if (k == 0) { float s = 0.f; for (int f = 0; f < FD; f++) s += sp1[f]; g_pj_sa[n] = s; }
    if (k == 1) { float s = 0.f; for (int f = 0; f < FD; f++) s += sp2[f]; g_pi_sa[n] = s; }
}

// ---------------- kernel B: fused pairwise main ----------------
__global__ __launch_bounds__(256, 3) void sake_main(
    const float* __restrict__ h, const float* __restrict__ x,
    const float* __restrict__ b_ew, const float* __restrict__ W_es,
    const float* __restrict__ b_es, const float* __restrict__ W_c1,
    const float* __restrict__ b_c1, const float* __restrict__ W_c2,
    const float* __restrict__ b_c2, const float* __restrict__ W_n,
    const float* __restrict__ b_n, float* __restrict__ out)
{
    extern __shared__ __align__(16) char dsm_raw[];
    SMEM* S = (SMEM*)dsm_raw;

    const int n_i = blockIdx.x;
    const int b = n_i >> 9;
    const int t = threadIdx.x;
    const int warp = t >> 5, lane = t & 31;

    // ---- stage Bp: pair-packed W_c1.  h = kt*8 + c4 + 4*kk ----
    for (int idx = t; idx < FD * FD; idx += 256) {
        int hh = idx >> 6, m = idx & 63;
        int kt = hh >> 3, rem = hh & 7, c4 = rem & 3, kk = rem >> 2;
        S->Bp[(((kt << 6) + m) << 3) + (c4 << 1) + kk] = __uint_as_float(tf32r(W_c1[idx]));
    }
    if (t < FD) {
        S->piew[t] = g_pi_ew[n_i * FD + t] + b_ew[t];
        S->pies[t] = g_pi_es[n_i * FD + t] + b_es[t];
        S->wes0[t] = W_es[t];
        S->bc1[t]  = b_c1[t];
        S->wc2[t]  = W_c2[t];
    }

    const float xi0 = x[n_i * 3 + 0], xi1 = x[n_i * 3 + 1], xi2 = x[n_i * 3 + 2];
    const float pi_sa_v = g_pi_sa[n_i];
    const float bc2v = b_c2[0];

    // ---- pass 1: per-j geometry + softmax numerators ----
    float esum = 0.f;
    for (int j = t; j < NN; j += 256) {
        float dx = x[(b * NN + j) * 3 + 0] - xi0;
        float dy = x[(b * NN + j) * 3 + 1] - xi1;
        float dz = x[(b * NN + j) * 3 + 2] - xi2;
        float d2 = dx * dx + dy * dy + dz * dz;
        float nrm = sqrtf(d2 + EPSV);
        float inv2 = 1.0f / (nrm * nrm + EPSV);
        S->xmxv[j] = make_float4(dx, dy, dz, inv2);
        S->filt[j] = 1.0f / (nrm + 0.1f);
        float en = __expf(nrm);
        esum += en;
        float sem = g_pj_sa[b * NN + j] + pi_sa_v;
        sem = (sem > 0.f) ? sem : 0.01f * sem;
        S->sw[j] = sem * en;
    }
#pragma unroll
    for (int o = 16; o; o >>= 1) esum += __shfl_xor_sync(0xffffffffu, esum, o);
    if (lane == 0) S->red[warp] = esum;
    __syncthreads();
    if (t == 0) {
        float s = 0.f;
#pragma unroll
        for (int w = 0; w < 8; w++) s += S->red[w];
        S->scal = 1.0f / s;
    }
    __syncthreads();

    // ---- pass 2: att_sum einsum (vectorized ew loads) ----
    {
        int k = t & 63, jb2 = t >> 6;
        float base = S->piew[k];
        const float4* pjew4 = (const float4*)(g_pjewT + (size_t)(b * FD + k) * NN + jb2 * 128);
        float a0 = 0.f, a1 = 0.f, a2 = 0.f;
        int j0 = jb2 * 128;
#pragma unroll 8
        for (int q = 0; q < 32; q++) {
            float4 e4 = pjew4[q];
            const int j = j0 + q * 4;
            float e; float4 xv;
            e = tanh_hw(e4.x + base) * S->xmxv[j + 0].w; xv = S->xmxv[j + 0];
            a0 = fmaf(e, xv.x, a0); a1 = fmaf(e, xv.y, a1); a2 = fmaf(e, xv.z, a2);
            e = tanh_hw(e4.y + base) * S->xmxv[j + 1].w; xv = S->xmxv[j + 1];
            a0 = fmaf(e, xv.x, a0); a1 = fmaf(e, xv.y, a1); a2 = fmaf(e, xv.z, a2);
            e = tanh_hw(e4.z + base) * S->xmxv[j + 2].w; xv = S->xmxv[j + 2];
            a0 = fmaf(e, xv.x, a0); a1 = fmaf(e, xv.y, a1); a2 = fmaf(e, xv.z, a2);
            e = tanh_hw(e4.w + base) * S->xmxv[j + 3].w; xv = S->xmxv[j + 3];
            a0 = fmaf(e, xv.x, a0); a1 = fmaf(e, xv.y, a1); a2 = fmaf(e, xv.z, a2);
        }
        S->attp[jb2][k][0] = a0; S->attp[jb2][k][1] = a1; S->attp[jb2][k][2] = a2;
    }
    __syncthreads();

    const float* pjes = g_pjesT + (size_t)(b * FD) * NN;
    float* Aw = S->A[warp];
    const u32 Aw_ad = (u32)__cvta_generic_to_shared(Aw);

    float xacc0 = 0.f, xacc1 = 0.f, xacc2 = 0.f;
    float agg0 = 0.f, agg1 = 0.f;     // lane owns h=lane, h=lane+32 (unscaled)
    const int r4 = lane >> 2, c4 = lane & 3;
    const int row = lane >> 1, sh2 = (lane & 1) << 5;   // he-gen mapping
    const float bc2l = (c4 == 0) ? bc2v : 0.f;          // bc2 applied once per j (on c4==0 lane)

    // ================= 4 subtiles of 16 j per warp =================
    for (int sub = 0; sub < 4; sub++) {
        const int jb = warp * 64 + sub * 16;

        // ---- he generation: 2 lanes per row, 32 h each ----
        {
            const int j = jb + row;
            const float filt = S->filt[j];
#pragma unroll
            for (int q = 0; q < 8; q++) {
                const int h0 = sh2 + q * 4;
                float p0 = pjes[(size_t)(h0 + 0) * NN + j] + fmaf(filt, S->wes0[h0 + 0], S->pies[h0 + 0]);
                float p1 = pjes[(size_t)(h0 + 1) * NN + j] + fmaf(filt, S->wes0[h0 + 1], S->pies[h0 + 1]);
                float p2 = pjes[(size_t)(h0 + 2) * NN + j] + fmaf(filt, S->wes0[h0 + 2], S->pies[h0 + 2]);
                float p3 = pjes[(size_t)(h0 + 3) * NN + j] + fmaf(filt, S->wes0[h0 + 3], S->pies[h0 + 3]);
                STS128S(Aw_ad + (u32)(row * APAD + h0) * 4,
                        tf32r(silu_hw(p0)), tf32r(silu_hw(p1)),
                        tf32r(silu_hw(p2)), tf32r(silu_hw(p3)));
            }
        }
        __syncwarp();

        // ---- MMA: D[16j x 64m] = he @ W_c1 + b_c1 (bias pre-loaded into D) ----
        float D[8][4];
#pragma unroll
        for (int nt = 0; nt < 8; nt++) {
            const float bA = S->bc1[nt * 8 + 2 * c4], bB = S->bc1[nt * 8 + 2 * c4 + 1];
            D[nt][0] = bA; D[nt][1] = bB; D[nt][2] = bA; D[nt][3] = bB;
        }
#pragma unroll
        for (int kt = 0; kt < 8; kt++) {
            const int kb = kt * 8;
            u32 a[4];
            a[0] = __float_as_uint(Aw[r4 * APAD + kb + c4]);
            a[1] = __float_as_uint(Aw[(r4 + 8) * APAD + kb + c4]);
            a[2] = __float_as_uint(Aw[r4 * APAD + kb + 4 + c4]);
            a[3] = __float_as_uint(Aw[(r4 + 8) * APAD + kb + 4 + c4]);
            const float* bprow = S->Bp + ((kt << 6) << 3) + (c4 << 1);
#pragma unroll
            for (int nt = 0; nt < 8; nt++) {
                const int nb = nt * 8;
                ull bv = *(const ull*)(bprow + ((nb + r4) << 3));
                mma_tf32_16x8x8(D[nt], a, (u32)bv, (u32)(bv >> 32));
            }
        }

        // ---- epilogue: silu -> dot wc2 -> shuffle-free partial-coord x accumulation ----
        {
            float cs0 = bc2l, cs1 = bc2l;
#pragma unroll
            for (int nt = 0; nt < 8; nt++) {
                const int c0 = nt * 8 + 2 * c4, c1 = c0 + 1;
                const float wcA = S->wc2[c0], wcB = S->wc2[c1];
                cs0 = fmaf(silu_hw(D[nt][0]), wcA, cs0);
                cs0 = fmaf(silu_hw(D[nt][1]), wcB, cs0);
                cs1 = fmaf(silu_hw(D[nt][2]), wcA, cs1);
                cs1 = fmaf(silu_hw(D[nt][3]), wcB, cs1);
            }
            // every lane contributes its partial; the end-of-kernel butterfly completes the sum
            const int j0 = jb + r4, j1 = j0 + 8;
            float4 xv0 = S->xmxv[j0];
            float4 xv1 = S->xmxv[j1];
            xacc0 = fmaf(xv0.x, cs0, xacc0);
            xacc1 = fmaf(xv0.y, cs0, xacc1);
            xacc2 = fmaf(xv0.z, cs0, xacc2);
            xacc0 = fmaf(xv1.x, cs1, xacc0);
            xacc1 = fmaf(xv1.y, cs1, xacc1);
            xacc2 = fmaf(xv1.z, cs1, xacc2);
        }

        // ---- h_e_agg from staged A columns (banks (4*jj+lane)%32: conflict-free) ----
#pragma unroll 4
        for (int jj = 0; jj < 16; jj++) {
            float w = S->sw[jb + jj];
            agg0 = fmaf(w, Aw[jj * APAD + lane],      agg0);
            agg1 = fmaf(w, Aw[jj * APAD + lane + 32], agg1);
        }
        __syncwarp();   // A reused next subtile
    }

    S->aggp[warp][lane]      = agg0;
    S->aggp[warp][lane + 32] = agg1;
#pragma unroll
    for (int o = 16; o; o >>= 1) {
        xacc0 += __shfl_xor_sync(0xffffffffu, xacc0, o);
        xacc1 += __shfl_xor_sync(0xffffffffu, xacc1, o);
        xacc2 += __shfl_xor_sync(0xffffffffu, xacc2, o);
    }
    if (lane == 0) { S->xp[warp][0] = xacc0; S->xp[warp][1] = xacc1; S->xp[warp][2] = xacc2; }
    __syncthreads();

    // ---- finalize att_norm and h_e_agg (softmax scale folded in here) ----
    if (t < FD) {
        float a0 = S->attp[0][t][0] + S->attp[1][t][0] + S->attp[2][t][0] + S->attp[3][t][0];
        float a1 = S->attp[0][t][1] + S->attp[1][t][1] + S->attp[2][t][1] + S->attp[3][t][1];
        float a2 = S->attp[0][t][2] + S->attp[1][t][2] + S->attp[2][t][2] + S->attp[3][t][2];
        S->attn[t] = sqrtf(a0 * a0 + a1 * a1 + a2 * a2 + EPSV);
        float ag = 0.f;
#pragma unroll
        for (int w2 = 0; w2 < 8; w2++) ag += S->aggp[w2][t];
        S->agg[t] = ag * S->scal;
    }
    __syncthreads();

    // ---- h_new = concat(h, agg, attn) @ W_n + b_n ----
    if (t < FD) {
        int m = t;
        float acc = b_n[m];
        const float* hi2 = h + (size_t)n_i * FD;
#pragma unroll 8
        for (int f = 0; f < FD; f++)  acc = fmaf(hi2[f],      W_n[f * FD + m], acc);
#pragma unroll 8
        for (int f = 0; f < FD; f++)  acc = fmaf(S->agg[f],   W_n[(FD + f) * FD + m], acc);
#pragma unroll 8
        for (int f = 0; f < FD; f++)  acc = fmaf(S->attn[f],  W_n[(2 * FD + f) * FD + m], acc);
        out[(size_t)n_i * FD + m] = acc;
    }
    if (t >= 64 && t < 67) {
        int c = t - 64;
        float xs = 0.f;
#pragma unroll
        for (int w2 = 0; w2 < 8; w2++) xs += S->xp[w2][c];
        out[(size_t)BN * FD + n_i * 3 + c] = x[n_i * 3 + c] + xs;
    }
}

extern "C" void kernel_launch(void* const* d_in, const int* in_sizes, int n_in,
                              void* d_out, int out_size) {
    const float* h    = (const float*)d_in[0];
    const float* x    = (const float*)d_in[1];
    const float* W_ew = (const float*)d_in[2];
    const float* b_ew = (const float*)d_in[3];
    const float* W_sa = (const float*)d_in[4];
    const float* W_es = (const float*)d_in[5];
    const float* b_es = (const float*)d_in[6];
    const float* W_c1 = (const float*)d_in[7];
    const float* b_c1 = (const float*)d_in[8];
    const float* W_c2 = (const float*)d_in[9];
    const float* b_c2 = (const float*)d_in[10];
    const float* W_n  = (const float*)d_in[11];
    const float* b_n  = (const float*)d_in[12];
    float* out = (float*)d_out;

    const int smem_bytes = (int)sizeof(SMEM);
    cudaFuncSetAttribute(sake_main, cudaFuncAttributeMaxDynamicSharedMemorySize, smem_bytes);

    sake_pre<<<BN, 64>>>(h, W_ew, W_es, W_sa);
    sake_main<<<BN, 256, smem_bytes>>>(h, x, b_ew, W_es, b_es, W_c1, b_c1, W_c2, b_c2, W_n, b_n, out);
}

// round 11
// speedup vs baseline: 1.2060x; 1.2060x over previous
#include <cuda_runtime.h>
#include <cuda_bf16.h>
#include <cstdint>
#include <cstddef>

#define NN 512
#define BN 2048
#define FD 64
#define EPSV 1e-14f

typedef unsigned long long ull;
typedef unsigned int u32;

// ---------------- scratch ----------------
__device__ float g_pj_ew[BN * FD];   // [n][k]  (coalesced column reads in pass 2)
__device__ float g_pi_ew[BN * FD];
__device__ float g_pjesT[BN * FD];   // [b][h][j]
__device__ float g_pi_es[BN * FD];
__device__ float g_pj_sa[BN];
__device__ float g_pi_sa[BN];

// ---------------- helpers ----------------
__device__ __forceinline__ float tanh_hw(float v) {
    float r; asm("tanh.approx.f32 %0, %1;" : "=f"(r) : "f"(v)); return r;
}
__device__ __forceinline__ float silu_hw(float v) {
    float m = 0.5f * v;
    return fmaf(m, tanh_hw(m), m);
}
__device__ __forceinline__ u32 tf32r(float f) {
    u32 r; asm("cvt.rna.tf32.f32 %0, %1;" : "=r"(r) : "f"(f)); return r;
}

__device__ __forceinline__ void mma_tf32_16x8x8(float d[4], const u32 a[4], u32 b0, u32 b1) {
    asm volatile("mma.sync.aligned.m16n8k8.row.col.f32.tf32.tf32.f32 "
        "{%0,%1,%2,%3}, {%4,%5,%6,%7}, {%8,%9}, {%0,%1,%2,%3};"
        : "+f"(d[0]), "+f"(d[1]), "+f"(d[2]), "+f"(d[3])
        : "r"(a[0]), "r"(a[1]), "r"(a[2]), "r"(a[3]), "r"(b0), "r"(b1));
}

#define STS128S(ad, r0, r1, r2, r3) \
    asm volatile("st.shared.v4.b32 [%0], {%1,%2,%3,%4};" :: "r"(ad), "r"(r0), "r"(r1), "r"(r2), "r"(r3) : "memory")

#define APAD 68   // 272B rows: 16B-aligned v4 stores; A-frag banks (4*r4+c4) distinct; agg banks (4*jj+lane) distinct

struct __align__(16) SMEM {
    float A[8][16 * APAD];   // per-warp he subtile (tf32 bits), [j(16)][h(64)]
    float Bp[8 * FD * 8];    // W_c1 pair-packed: [kt(8)][m(64)][c4(4)][kk(2)]  (16KB)
    float xmx[NN * 3];
    float inv2[NN];
    float filt[NN];
    float sw[NN];
    float piew[FD], pies[FD], wes0[FD], bc1[FD], wc2[FD];
    float attp[4][FD][3];
    float aggp[8][FD];
    float agg[FD], attn[FD];
    float xp[8][3];
    float red[8];
    float scal;
};

// ---------------- kernel A: node-level projections ----------------
__global__ void sake_pre(const float* __restrict__ h,
                         const float* __restrict__ W_ew,
                         const float* __restrict__ W_es,
                         const float* __restrict__ W_sa) {
    int n = blockIdx.x;
    int k = threadIdx.x;
    __shared__ float sh[FD];
    __shared__ float sp1[FD], sp2[FD];
    sh[k] = h[n * FD + k];
    __syncthreads();
    float a_jew = 0.f, a_iew = 0.f, a_jes = 0.f, a_ies = 0.f;
#pragma unroll 8
    for (int f = 0; f < FD; f++) {
        float hf = sh[f];
        a_jew = fmaf(hf, W_ew[f * FD + k], a_jew);
        a_iew = fmaf(hf, W_ew[(FD + f) * FD + k], a_iew);
        a_jes = fmaf(hf, W_es[(1 + f) * FD + k], a_jes);
        a_ies = fmaf(hf, W_es[(1 + FD + f) * FD + k], a_ies);
    }
    g_pj_ew[n * FD + k] = a_jew;
    g_pi_ew[n * FD + k] = a_iew;
    int b = n >> 9, j = n & 511;
    g_pjesT[(b * FD + k) * NN + j] = a_jes;
    g_pi_es[n * FD + k] = a_ies;
    sp1[k] = sh[k] * W_sa[k];
    sp2[k] = sh[k] * W_sa[FD + k];
    __syncthreads();
    if (k == 0) { float s = 0.f; for (int f = 0; f < FD; f++) s += sp1[f]; g_pj_sa[n] = s; }
    if (k == 1) { float s = 0.f; for (int f = 0; f < FD; f++) s += sp2[f]; g_pi_sa[n] = s; }
}

// ---------------- kernel B: fused pairwise main ----------------
__global__ __launch_bounds__(256, 3) void sake_main(
    const float* __restrict__ h, const float* __restrict__ x,
    const float* __restrict__ b_ew, const float* __restrict__ W_es,
    const float* __restrict__ b_es, const float* __restrict__ W_c1,
    const float* __restrict__ b_c1, const float* __restrict__ W_c2,
    const float* __restrict__ b_c2, const float* __restrict__ W_n,
    const float* __restrict__ b_n, float* __restrict__ out)
{
    extern __shared__ __align__(16) char dsm_raw[];
    SMEM* S = (SMEM*)dsm_raw;

    const int n_i = blockIdx.x;
    const int b = n_i >> 9;
    const int t = threadIdx.x;
    const int warp = t >> 5, lane = t & 31;

    // ---- stage Bp: pair-packed W_c1.  h = kt*8 + c4 + 4*kk ----
    for (int idx = t; idx < FD * FD; idx += 256) {
        int hh = idx >> 6, m = idx & 63;
        int kt = hh >> 3, rem = hh & 7, c4 = rem & 3, kk = rem >> 2;
        S->Bp[(((kt << 6) + m) << 3) + (c4 << 1) + kk] = __uint_as_float(tf32r(W_c1[idx]));
    }
    if (t < FD) {
        S->piew[t] = g_pi_ew[n_i * FD + t] + b_ew[t];
        S->pies[t] = g_pi_es[n_i * FD + t] + b_es[t];
        S->wes0[t] = W_es[t];
        S->bc1[t]  = b_c1[t];
        S->wc2[t]  = W_c2[t];
    }

    const float xi0 = x[n_i * 3 + 0], xi1 = x[n_i * 3 + 1], xi2 = x[n_i * 3 + 2];
    const float pi_sa_v = g_pi_sa[n_i];
    const float bc2v = b_c2[0];

    // ---- pass 1: per-j geometry + softmax numerators ----
    float esum = 0.f;
    for (int j = t; j < NN; j += 256) {
        float dx = x[(b * NN + j) * 3 + 0] - xi0;
        float dy = x[(b * NN + j) * 3 + 1] - xi1;
        float dz = x[(b * NN + j) * 3 + 2] - xi2;
        float d2 = dx * dx + dy * dy + dz * dz;
        float nrm = sqrtf(d2 + EPSV);
        S->xmx[j * 3 + 0] = dx; S->xmx[j * 3 + 1] = dy; S->xmx[j * 3 + 2] = dz;
        S->inv2[j] = 1.0f / (nrm * nrm + EPSV);
        S->filt[j] = 1.0f / (nrm + 0.1f);
        float en = __expf(nrm);
        esum += en;
        float sem = g_pj_sa[b * NN + j] + pi_sa_v;
        sem = (sem > 0.f) ? sem : 0.01f * sem;
        S->sw[j] = sem * en;
    }
#pragma unroll
    for (int o = 16; o; o >>= 1) esum += __shfl_xor_sync(0xffffffffu, esum, o);
    if (lane == 0) S->red[warp] = esum;
    __syncthreads();
    if (t == 0) {
        float s = 0.f;
#pragma unroll
        for (int w = 0; w < 8; w++) s += S->red[w];
        S->scal = 1.0f / s;
    }
    __syncthreads();

    // ---- pass 2: att_sum einsum (coalesced column reads of g_pj_ew) ----
    {
        int k = t & 63, jb2 = t >> 6;
        float base = S->piew[k];
        const float* pjew = g_pj_ew + (size_t)(b * NN) * FD + k;
        float a0 = 0.f, a1 = 0.f, a2 = 0.f;
        int j0 = jb2 * 128;
#pragma unroll 4
        for (int jj = 0; jj < 128; jj++) {
            int j = j0 + jj;
            float e = tanh_hw(pjew[(size_t)j * FD] + base);
            float ei = e * S->inv2[j];
            a0 = fmaf(ei, S->xmx[j * 3 + 0], a0);
            a1 = fmaf(ei, S->xmx[j * 3 + 1], a1);
            a2 = fmaf(ei, S->xmx[j * 3 + 2], a2);
        }
        S->attp[jb2][k][0] = a0; S->attp[jb2][k][1] = a1; S->attp[jb2][k][2] = a2;
    }
    __syncthreads();

    const float* pjes = g_pjesT + (size_t)(b * FD) * NN;
    float* Aw = S->A[warp];
    const u32 Aw_ad = (u32)__cvta_generic_to_shared(Aw);

    float xacc0 = 0.f, xacc1 = 0.f, xacc2 = 0.f;
    float agg0 = 0.f, agg1 = 0.f;     // lane owns h=lane, h=lane+32 (unscaled)
    const int r4 = lane >> 2, c4 = lane & 3;
    const int row = lane >> 1, sh2 = (lane & 1) << 5;   // he-gen mapping
    const float bc2l = (c4 == 0) ? bc2v : 0.f;          // bc2 applied once per j (on c4==0 lane)

    // ================= 4 subtiles of 16 j per warp =================
    for (int sub = 0; sub < 4; sub++) {
        const int jb = warp * 64 + sub * 16;

        // ---- he generation: 2 lanes per row, 32 h each ----
        {
            const int j = jb + row;
            const float filt = S->filt[j];
#pragma unroll
            for (int q = 0; q < 8; q++) {
                const int h0 = sh2 + q * 4;
                float p0 = pjes[(size_t)(h0 + 0) * NN + j] + fmaf(filt, S->wes0[h0 + 0], S->pies[h0 + 0]);
                float p1 = pjes[(size_t)(h0 + 1) * NN + j] + fmaf(filt, S->wes0[h0 + 1], S->pies[h0 + 1]);
                float p2 = pjes[(size_t)(h0 + 2) * NN + j] + fmaf(filt, S->wes0[h0 + 2], S->pies[h0 + 2]);
                float p3 = pjes[(size_t)(h0 + 3) * NN + j] + fmaf(filt, S->wes0[h0 + 3], S->pies[h0 + 3]);
                STS128S(Aw_ad + (u32)(row * APAD + h0) * 4,
                        tf32r(silu_hw(p0)), tf32r(silu_hw(p1)),
                        tf32r(silu_hw(p2)), tf32r(silu_hw(p3)));
            }
        }
        __syncwarp();

        // ---- MMA: D[16j x 64m] = he @ W_c1 + b_c1 (bias pre-loaded into D) ----
        float D[8][4];
#pragma unroll
        for (int nt = 0; nt < 8; nt++) {
            const float bA = S->bc1[nt * 8 + 2 * c4], bB = S->bc1[nt * 8 + 2 * c4 + 1];
            D[nt][0] = bA; D[nt][1] = bB; D[nt][2] = bA; D[nt][3] = bB;
        }
#pragma unroll
        for (int kt = 0; kt < 8; kt++) {
            const int kb = kt * 8;
            u32 a[4];
            a[0] = __float_as_uint(Aw[r4 * APAD + kb + c4]);
            a[1] = __float_as_uint(Aw[(r4 + 8) * APAD + kb + c4]);
            a[2] = __float_as_uint(Aw[r4 * APAD + kb + 4 + c4]);
            a[3] = __float_as_uint(Aw[(r4 + 8) * APAD + kb + 4 + c4]);
            const float* bprow = S->Bp + ((kt << 6) << 3) + (c4 << 1);
#pragma unroll
            for (int nt = 0; nt < 8; nt++) {
                const int nb = nt * 8;
                ull bv = *(const ull*)(bprow + ((nb + r4) << 3));
                mma_tf32_16x8x8(D[nt], a, (u32)bv, (u32)(bv >> 32));
            }
        }

        // ---- epilogue: silu -> dot wc2 -> shuffle-free partial-coord x accumulation ----
        {
            float cs0 = bc2l, cs1 = bc2l;
#pragma unroll
            for (int nt = 0; nt < 8; nt++) {
                const int c0 = nt * 8 + 2 * c4, c1 = c0 + 1;
                const float wcA = S->wc2[c0], wcB = S->wc2[c1];
                cs0 = fmaf(silu_hw(D[nt][0]), wcA, cs0);
                cs0 = fmaf(silu_hw(D[nt][1]), wcB, cs0);
                cs1 = fmaf(silu_hw(D[nt][2]), wcA, cs1);
                cs1 = fmaf(silu_hw(D[nt][3]), wcB, cs1);
            }
            // every lane folds its PARTIAL coord into xacc; the end-of-kernel
            // 32-lane butterfly completes the j-sums AND the c4-sums together.
            const int j0 = jb + r4, j1 = j0 + 8;
            xacc0 = fmaf(S->xmx[j0 * 3 + 0], cs0, xacc0);
            xacc1 = fmaf(S->xmx[j0 * 3 + 1], cs0, xacc1);
            xacc2 = fmaf(S->xmx[j0 * 3 + 2], cs0, xacc2);
            xacc0 = fmaf(S->xmx[j1 * 3 + 0], cs1, xacc0);
            xacc1 = fmaf(S->xmx[j1 * 3 + 1], cs1, xacc1);
            xacc2 = fmaf(S->xmx[j1 * 3 + 2], cs1, xacc2);
        }

        // ---- h_e_agg from staged A columns (banks (4*jj+lane)%32: conflict-free) ----
#pragma unroll 4
        for (int jj = 0; jj < 16; jj++) {
            float w = S->sw[jb + jj];
            agg0 = fmaf(w, Aw[jj * APAD + lane],      agg0);
            agg1 = fmaf(w, Aw[jj * APAD + lane + 32], agg1);
        }
        __syncwarp();   // A reused next subtile
    }

    S->aggp[warp][lane]      = agg0;
    S->aggp[warp][lane + 32] = agg1;
#pragma unroll
    for (int o = 16; o; o >>= 1) {
        xacc0 += __shfl_xor_sync(0xffffffffu, xacc0, o);
        xacc1 += __shfl_xor_sync(0xffffffffu, xacc1, o);
        xacc2 += __shfl_xor_sync(0xffffffffu, xacc2, o);
    }
    if (lane == 0) { S->xp[warp][0] = xacc0; S->xp[warp][1] = xacc1; S->xp[warp][2] = xacc2; }
    __syncthreads();

    // ---- finalize att_norm and h_e_agg (softmax scale folded in here) ----
    if (t < FD) {
        float a0 = S->attp[0][t][0] + S->attp[1][t][0] + S->attp[2][t][0] + S->attp[3][t][0];
        float a1 = S->attp[0][t][1] + S->attp[1][t][1] + S->attp[2][t][1] + S->attp[3][t][1];
        float a2 = S->attp[0][t][2] + S->attp[1][t][2] + S->attp[2][t][2] + S->attp[3][t][2];
        S->attn[t] = sqrtf(a0 * a0 + a1 * a1 + a2 * a2 + EPSV);
        float ag = 0.f;
#pragma unroll
        for (int w2 = 0; w2 < 8; w2++) ag += S->aggp[w2][t];
        S->agg[t] = ag * S->scal;
    }
    __syncthreads();

    // ---- h_new = concat(h, agg, attn) @ W_n + b_n ----
    if (t < FD) {
        int m = t;
        float acc = b_n[m];
        const float* hi2 = h + (size_t)n_i * FD;
#pragma unroll 8
    for (int f = 0; f < FD; f++)  acc = fmaf(hi2[f],      W_n[f * FD + m], acc);
#pragma unroll 8
        for (int f = 0; f < FD; f++)  acc = fmaf(S->agg[f],   W_n[(FD + f) * FD + m], acc);
#pragma unroll 8
        for (int f = 0; f < FD; f++)  acc = fmaf(S->attn[f],  W_n[(2 * FD + f) * FD + m], acc);
        out[(size_t)n_i * FD + m] = acc;
    }
    if (t >= 64 && t < 67) {
        int c = t - 64;
        float xs = 0.f;
#pragma unroll
        for (int w2 = 0; w2 < 8; w2++) xs += S->xp[w2][c];
        out[(size_t)BN * FD + n_i * 3 + c] = x[n_i * 3 + c] + xs;
    }
}

extern "C" void kernel_launch(void* const* d_in, const int* in_sizes, int n_in,
                              void* d_out, int out_size) {
    const float* h    = (const float*)d_in[0];
    const float* x    = (const float*)d_in[1];
    const float* W_ew = (const float*)d_in[2];
    const float* b_ew = (const float*)d_in[3];
    const float* W_sa = (const float*)d_in[4];
    const float* W_es = (const float*)d_in[5];
    const float* b_es = (const float*)d_in[6];
    const float* W_c1 = (const float*)d_in[7];
    const float* b_c1 = (const float*)d_in[8];
    const float* W_c2 = (const float*)d_in[9];
    const float* b_c2 = (const float*)d_in[10];
    const float* W_n  = (const float*)d_in[11];
    const float* b_n  = (const float*)d_in[12];
    float* out = (float*)d_out;

    const int smem_bytes = (int)sizeof(SMEM);
    cudaFuncSetAttribute(sake_main, cudaFuncAttributeMaxDynamicSharedMemorySize, smem_bytes);

    sake_pre<<<BN, 64>>>(h, W_ew, W_es, W_sa);
    sake_main<<<BN, 256, smem_bytes>>>(h, x, b_ew, W_es, b_es, W_c1, b_c1, W_c2, b_c2, W_n, b_n, out);
}